// round 2
// baseline (speedup 1.0000x reference)
#include <cuda_runtime.h>
#include <cstdint>

// ============================================================================
// CalibratedProjectiveLinear: y = (x @ W^T + bias) * scale
//   W[o,i] = sign[o,i] * exp(log_min + (255-stored[o,i])/254 * (log_max-log_min))
// x[512,4096] f32, stored/sign[11008,4096] i32, scale/bias[11008] f32.
//
// sm_103 (no 'a' features available in this build): Ampere-style tf32
// mma.sync GEMM (fallback HMMA on Blackwell) + cp.async double buffering.
// QINS decode via 256-entry tf32 LUT + sign-bit XOR, fused into the mainloop.
// ============================================================================

namespace {
constexpr int B_   = 512;
constexpr int IN_  = 4096;
constexpr int OUT_ = 11008;
constexpr int MT   = 128;            // CTA tile M
constexpr int NT   = 128;            // CTA tile N
constexpr int KC   = 32;             // K per pipeline stage
constexpr int NITER = IN_ / KC;      // 128
constexpr int MTILES = B_ / MT;      // 4
constexpr int NTILES = OUT_ / NT;    // 86
constexpr int GRID  = MTILES * NTILES;  // 344

constexpr int RPAD = 36;             // padded row stride in floats (36 = 4 mod 32)

// smem layout (bytes)
constexpr int OFF_LUT = 0;                        // 256 entries x 4 replicas x 4B
constexpr int LUT_B   = 256 * 4 * 4;              // 4096
constexpr int OFF_BS  = OFF_LUT + LUT_B;          // bias[128], scale[128]
constexpr int BS_B    = 2 * NT * 4;               // 1024
constexpr int OFF_STG = OFF_BS + BS_B;            // 5120
constexpr int XT_B    = MT * RPAD * 4;            // 18432 (x tile, padded)
constexpr int WT_B    = NT * RPAD * 4;            // 18432 (stored -> decoded W, padded)
constexpr int SG_B    = NT * KC * 4;              // 16384 (sign tile, compact)
constexpr int STG_B   = XT_B + WT_B + SG_B;       // 53248
constexpr int SMEM_TOTAL = OFF_STG + 2 * STG_B;   // 111616 -> 2 CTAs/SM
}  // namespace

__device__ float g_xr[B_ * IN_];  // x pre-rounded to tf32 (RN), 8 MB scratch

// ----------------------------------------------------------------------------
__device__ __forceinline__ uint32_t smem_u32(const void* p) {
    return (uint32_t)__cvta_generic_to_shared(p);
}
__device__ __forceinline__ uint32_t f2tf32(float f) {
    uint32_t u; asm("cvt.rna.tf32.f32 %0, %1;" : "=r"(u) : "f"(f)); return u;
}
__device__ __forceinline__ void cp16(uint32_t dst, const void* src) {
    asm volatile("cp.async.cg.shared.global [%0], [%1], 16;"
                 :: "r"(dst), "l"(src) : "memory");
}
__device__ __forceinline__ void cp_commit() {
    asm volatile("cp.async.commit_group;" ::: "memory");
}
__device__ __forceinline__ void mma_tf32(float* c, const uint32_t* a, const uint32_t* b) {
    asm volatile(
        "mma.sync.aligned.m16n8k8.row.col.f32.tf32.tf32.f32 "
        "{%0,%1,%2,%3}, {%4,%5,%6,%7}, {%8,%9}, {%0,%1,%2,%3};"
        : "+f"(c[0]), "+f"(c[1]), "+f"(c[2]), "+f"(c[3])
        : "r"(a[0]), "r"(a[1]), "r"(a[2]), "r"(a[3]), "r"(b[0]), "r"(b[1]));
}

// ----------------------------------------------------------------------------
// Pre-kernel: round x to tf32 (round-to-nearest) so HW RZ-truncation is a no-op.
__global__ void __launch_bounds__(256) xr_kernel(const float* __restrict__ x) {
    int i = blockIdx.x * 256 + threadIdx.x;
    g_xr[i] = __uint_as_float(f2tf32(x[i]));
}

// ----------------------------------------------------------------------------
__global__ void __launch_bounds__(256, 2) qins_gemm_kernel(
    const int* __restrict__ stored, const int* __restrict__ sgn,
    const float* __restrict__ lmnp, const float* __restrict__ lmxp,
    const float* __restrict__ scale, const float* __restrict__ bias,
    float* __restrict__ out) {
    extern __shared__ char smem[];
    const uint32_t sb = smem_u32(smem);
    const int tid  = threadIdx.x;
    const int lane = tid & 31;
    const int warp = tid >> 5;
    const int warp_m = warp & 3;        // 4 warps along M
    const int warp_n = warp >> 2;       // 2 warps along N
    const int m0 = (blockIdx.x % MTILES) * MT;   // adjacent bids share N-band? no:
    const int n0 = (blockIdx.x / MTILES) * NT;   // adjacent bids = same n0, diff m0 -> W L2 reuse

    uint32_t* lut  = (uint32_t*)(smem + OFF_LUT);
    float*    bi_s = (float*)(smem + OFF_BS);
    float*    sc_s = (float*)(smem + OFF_BS + NT * 4);

    // LUT (tf32-rounded, 4 bank replicas) + per-band bias/scale
    {
        const float lmn = *lmnp, lmx = *lmxp;
        const float d = (lmx - lmn) * (1.0f / 254.0f);
        const uint32_t v = f2tf32(expf(lmn + (255.0f - (float)tid) * d));
        #pragma unroll
        for (int r = 0; r < 4; ++r) lut[tid * 4 + r] = v;
        if (tid < NT) {
            bi_s[tid] = bias[n0 + tid];
            sc_s[tid] = scale[n0 + tid];
        }
    }

    // ---- stage load issue (12 x 16B cp.async per thread) ----
    auto issue_stage = [&](int s, int k0) {
        const uint32_t stg = sb + OFF_STG + s * STG_B;
        #pragma unroll
        for (int j = 0; j < 4; ++j) {
            const int q = tid + j * 256;        // 0..1023 chunk id
            const int r = q >> 3;               // tile row 0..127
            const int c = q & 7;                // 16B chunk in row
            const uint32_t po = (uint32_t)(r * RPAD + c * 4) * 4;
            cp16(stg + po,                g_xr   + (size_t)(m0 + r) * IN_ + k0 + c * 4);
            cp16(stg + XT_B + po,         stored + (size_t)(n0 + r) * IN_ + k0 + c * 4);
            cp16(stg + XT_B + WT_B + q * 16, sgn + (size_t)(n0 + r) * IN_ + k0 + c * 4);
        }
        cp_commit();
    };

    issue_stage(0, 0);
    issue_stage(1, KC);
    __syncthreads();  // also covers LUT/bias/scale fill

    float acc[2][8][4];
    #pragma unroll
    for (int mf = 0; mf < 2; ++mf)
        #pragma unroll
        for (int nf = 0; nf < 8; ++nf)
            #pragma unroll
            for (int r = 0; r < 4; ++r) acc[mf][nf][r] = 0.0f;

    const int lr = tid & 3;  // LUT replica
    const int arow = warp_m * 32 + (lane >> 2);      // A frag base row (local)
    const int brow = warp_n * 64 + (lane >> 2);      // B frag base n (local)
    const int kq   = lane & 3;                       // frag k offset

    for (int it = 0; it < NITER; ++it) {
        const int s = it & 1;
        if (it < NITER - 1) asm volatile("cp.async.wait_group 1;" ::: "memory");
        else                asm volatile("cp.async.wait_group 0;" ::: "memory");
        __syncthreads();

        char* stg = smem + OFF_STG + s * STG_B;
        // ---- decode: stored(int) -> tf32 weight, in place, sign via bit31 ----
        {
            const uint4* sgp = (const uint4*)(stg + XT_B + WT_B);
            #pragma unroll
            for (int j = 0; j < 4; ++j) {
                const int q = tid + j * 256;
                const int r = q >> 3;
                const int c = q & 7;
                uint4* wp = (uint4*)(stg + XT_B + (uint32_t)(r * RPAD + c * 4) * 4);
                uint4 wv = *wp;
                const uint4 sv = sgp[q];
                wv.x = lut[(wv.x & 0xFF) * 4 + lr] ^ (sv.x & 0x80000000u);
                wv.y = lut[(wv.y & 0xFF) * 4 + lr] ^ (sv.y & 0x80000000u);
                wv.z = lut[(wv.z & 0xFF) * 4 + lr] ^ (sv.z & 0x80000000u);
                wv.w = lut[(wv.w & 0xFF) * 4 + lr] ^ (sv.w & 0x80000000u);
                *wp = wv;
            }
        }
        __syncthreads();

        // ---- mma over 4 k-steps of 8 ----
        {
            const uint32_t* Xs = (const uint32_t*)stg;
            const uint32_t* Ws = (const uint32_t*)(stg + XT_B);
            #pragma unroll
            for (int ks = 0; ks < 4; ++ks) {
                const int k = ks * 8 + kq;
                uint32_t a[2][4];
                #pragma unroll
                for (int mf = 0; mf < 2; ++mf) {
                    const int rr = arow + mf * 16;
                    a[mf][0] = Xs[rr * RPAD + k];
                    a[mf][1] = Xs[(rr + 8) * RPAD + k];
                    a[mf][2] = Xs[rr * RPAD + k + 4];
                    a[mf][3] = Xs[(rr + 8) * RPAD + k + 4];
                }
                #pragma unroll
                for (int nf = 0; nf < 8; ++nf) {
                    uint32_t b[2];
                    const int nn = brow + nf * 8;
                    b[0] = Ws[nn * RPAD + k];
                    b[1] = Ws[nn * RPAD + k + 4];
                    mma_tf32(acc[0][nf], a[0], b);
                    mma_tf32(acc[1][nf], a[1], b);
                }
            }
        }
        __syncthreads();  // all warps done reading stage s before overwrite

        if (it + 2 < NITER) issue_stage(s, (it + 2) * KC);
    }

    // ---- epilogue: (acc + bias) * scale ----
    #pragma unroll
    for (int mf = 0; mf < 2; ++mf) {
        const int row = m0 + warp_m * 32 + mf * 16 + (lane >> 2);
        #pragma unroll
        for (int nf = 0; nf < 8; ++nf) {
            const int cl = warp_n * 64 + nf * 8 + (lane & 3) * 2;  // CTA-local n
            float2 v0, v1;
            v0.x = (acc[mf][nf][0] + bi_s[cl])     * sc_s[cl];
            v0.y = (acc[mf][nf][1] + bi_s[cl + 1]) * sc_s[cl + 1];
            v1.x = (acc[mf][nf][2] + bi_s[cl])     * sc_s[cl];
            v1.y = (acc[mf][nf][3] + bi_s[cl + 1]) * sc_s[cl + 1];
            *(float2*)(out + (size_t)row * OUT_ + n0 + cl)       = v0;
            *(float2*)(out + (size_t)(row + 8) * OUT_ + n0 + cl) = v1;
        }
    }
}

// ----------------------------------------------------------------------------
extern "C" void kernel_launch(void* const* d_in, const int* in_sizes, int n_in,
                              void* d_out, int out_size) {
    const float* x      = (const float*)d_in[0];
    const int*   stored = (const int*)d_in[1];
    const int*   sgn    = (const int*)d_in[2];
    const float* lmn    = (const float*)d_in[3];
    const float* lmx    = (const float*)d_in[4];
    const float* scale  = (const float*)d_in[5];
    const float* bias   = (const float*)d_in[6];
    float* out = (float*)d_out;

    cudaFuncSetAttribute(qins_gemm_kernel,
                         cudaFuncAttributeMaxDynamicSharedMemorySize, SMEM_TOTAL);

    xr_kernel<<<(B_ * IN_) / 256, 256>>>(x);
    qins_gemm_kernel<<<GRID, 256, SMEM_TOTAL>>>(stored, sgn, lmn, lmx, scale, bias, out);
}

// round 6
// speedup vs baseline: 1.1745x; 1.1745x over previous
#include <cuda_runtime.h>
#include <cstdint>

// ============================================================================
// CalibratedProjectiveLinear: y = (x @ W^T + bias) * scale
//   W[o,i] = sign[o,i] * exp(log_min + (255-stored[o,i])/254 * (log_max-log_min))
// R5 (= audited R3/R4 re-bench after two broker failures): tf32 mma.sync +
// ldmatrix.x4 fragments over swizzled 64B rows, 3-phase pipeline
// (fill / decode / mma on different stages), ONE __syncthreads per iteration.
// QINS decode via 256-entry tf32 LUT + sign-bit XOR.
// ============================================================================

namespace {
constexpr int B_   = 512;
constexpr int IN_  = 4096;
constexpr int OUT_ = 11008;
constexpr int MT   = 128;
constexpr int NT   = 128;
constexpr int KC   = 16;               // K per stage (64B rows)
constexpr int NITER = IN_ / KC;        // 256
constexpr int MTILES = B_ / MT;        // 4
constexpr int GRID  = MTILES * (OUT_ / NT);  // 344

// smem layout (bytes)
constexpr int OFF_LUT = 0;                       // 256 entries x 4 replicas x 4B
constexpr int OFF_BS  = 4096;                    // bias[128] + scale[128]
constexpr int OFF_X   = 5120;                    // X ring: 4 stages x 8192
constexpr int OFF_W   = OFF_X + 4 * 8192;       // Wdec ring: 2 stages x 8192
constexpr int OFF_R   = OFF_W + 2 * 8192;       // raw ring: 3 x (stored 8K + sign 8K)
constexpr int SMEM_TOTAL = OFF_R + 3 * 16384;   // 103424 -> 2 CTAs/SM
}  // namespace

__device__ float g_xr[B_ * IN_];  // x pre-rounded to tf32 (RN)

// ----------------------------------------------------------------------------
__device__ __forceinline__ uint32_t smem_u32(const void* p) {
    return (uint32_t)__cvta_generic_to_shared(p);
}
__device__ __forceinline__ uint32_t f2tf32(float f) {
    uint32_t u; asm("cvt.rna.tf32.f32 %0, %1;" : "=r"(u) : "f"(f)); return u;
}
__device__ __forceinline__ uint32_t sw64(uint32_t o) { return o ^ ((o >> 3) & 0x30u); }
__device__ __forceinline__ void cp16(uint32_t dst, const void* src) {
    asm volatile("cp.async.cg.shared.global [%0], [%1], 16;"
                 :: "r"(dst), "l"(src) : "memory");
}
__device__ __forceinline__ void cp_commit() {
    asm volatile("cp.async.commit_group;" ::: "memory");
}
__device__ __forceinline__ void ldsm4(uint32_t* r, uint32_t addr) {
    asm volatile("ldmatrix.sync.aligned.m8n8.x4.shared.b16 {%0,%1,%2,%3}, [%4];"
                 : "=r"(r[0]), "=r"(r[1]), "=r"(r[2]), "=r"(r[3]) : "r"(addr));
}
__device__ __forceinline__ void mma_tf32(float* c, const uint32_t* a, const uint32_t* b) {
    asm volatile(
        "mma.sync.aligned.m16n8k8.row.col.f32.tf32.tf32.f32 "
        "{%0,%1,%2,%3}, {%4,%5,%6,%7}, {%8,%9}, {%0,%1,%2,%3};"
        : "+f"(c[0]), "+f"(c[1]), "+f"(c[2]), "+f"(c[3])
        : "r"(a[0]), "r"(a[1]), "r"(a[2]), "r"(a[3]), "r"(b[0]), "r"(b[1]));
}

// ----------------------------------------------------------------------------
__global__ void __launch_bounds__(256) xr_kernel(const float* __restrict__ x) {
    int i = blockIdx.x * 256 + threadIdx.x;
    g_xr[i] = __uint_as_float(f2tf32(x[i]));
}

// ----------------------------------------------------------------------------
__global__ void __launch_bounds__(256, 2) qins_gemm_kernel(
    const int* __restrict__ stored, const int* __restrict__ sgn,
    const float* __restrict__ lmnp, const float* __restrict__ lmxp,
    const float* __restrict__ scale, const float* __restrict__ bias,
    float* __restrict__ out) {
    extern __shared__ char smem[];
    const uint32_t sb = smem_u32(smem);
    const int tid  = threadIdx.x;
    const int lane = tid & 31;
    const int warp = tid >> 5;
    const int warp_m = warp & 3;
    const int warp_n = warp >> 2;
    const int m0 = (blockIdx.x & 3) * MT;
    const int n0 = (blockIdx.x >> 2) * NT;

    uint32_t* lut  = (uint32_t*)(smem + OFF_LUT);
    float*    bi_s = (float*)(smem + OFF_BS);
    float*    sc_s = (float*)(smem + OFF_BS + NT * 4);

    {   // LUT (tf32, 4 replicas) + bias/scale
        const float lmn = *lmnp, lmx = *lmxp;
        const float d = (lmx - lmn) * (1.0f / 254.0f);
        const uint32_t v = f2tf32(expf(lmn + (255.0f - (float)tid) * d));
        #pragma unroll
        for (int r = 0; r < 4; ++r) lut[tid * 4 + r] = v;
        if (tid < NT) { bi_s[tid] = bias[n0 + tid]; sc_s[tid] = scale[n0 + tid]; }
    }

    // per-thread fill/decode chunk coords (ownership: fill == decode)
    const int q0 = tid, q1 = tid + 256;  // 16B chunks (512 per 8KB stage)
    const int r0c = q0 >> 2, c0c = q0 & 3, r1c = q1 >> 2, c1c = q1 & 3;

    auto fill = [&](int st) {
        const int k0 = st * KC;
        const uint32_t Xd = sb + OFF_X + (uint32_t)(st & 3) * 8192;
        const uint32_t Rd = sb + OFF_R + (uint32_t)(st % 3) * 16384;
        cp16(Xd + sw64(q0 * 16), g_xr + (size_t)(m0 + r0c) * IN_ + k0 + c0c * 4);
        cp16(Xd + sw64(q1 * 16), g_xr + (size_t)(m0 + r1c) * IN_ + k0 + c1c * 4);
        cp16(Rd + q0 * 16,        stored + (size_t)(n0 + r0c) * IN_ + k0 + c0c * 4);
        cp16(Rd + q1 * 16,        stored + (size_t)(n0 + r1c) * IN_ + k0 + c1c * 4);
        cp16(Rd + 8192 + q0 * 16, sgn    + (size_t)(n0 + r0c) * IN_ + k0 + c0c * 4);
        cp16(Rd + 8192 + q1 * 16, sgn    + (size_t)(n0 + r1c) * IN_ + k0 + c1c * 4);
    };

    const int lrp = tid & 3;  // LUT replica index
    auto decode = [&](int st) {
        char* R = smem + OFF_R + (size_t)(st % 3) * 16384;
        char* W = smem + OFF_W + (size_t)(st & 1) * 8192;
        #pragma unroll
        for (int j = 0; j < 2; ++j) {
            const int q = j ? q1 : q0;
            const uint4 sv = *(const uint4*)(R + q * 16);
            const uint4 gv = *(const uint4*)(R + 8192 + q * 16);
            uint4 w;
            w.x = lut[(sv.x & 0xFF) * 4 + lrp] ^ (gv.x & 0x80000000u);
            w.y = lut[(sv.y & 0xFF) * 4 + lrp] ^ (gv.y & 0x80000000u);
            w.z = lut[(sv.z & 0xFF) * 4 + lrp] ^ (gv.z & 0x80000000u);
            w.w = lut[(sv.w & 0xFF) * 4 + lrp] ^ (gv.w & 0x80000000u);
            *(uint4*)(W + sw64((uint32_t)q * 16)) = w;
        }
    };

    // fragment accumulators
    float acc[2][8][4];
    #pragma unroll
    for (int mf = 0; mf < 2; ++mf)
        #pragma unroll
        for (int nf = 0; nf < 8; ++nf)
            #pragma unroll
            for (int r = 0; r < 4; ++r) acc[mf][nf][r] = 0.0f;

    // precompute ldmatrix lane-pointer offsets (stage-invariant)
    // A x4 tiles: (m0-7,k0-3)(m8-15,k0-3)(m0-7,k4-7)(m8-15,k4-7)
    const int a_row = warp_m * 32 + ((lane >> 3) & 1) * 8 + (lane & 7);
    const int a_sel = lane >> 4;
    // B x4 tiles: (n0-7,k0-3)(n0-7,k4-7)(n8-15,k0-3)(n8-15,k4-7)
    const int b_row = warp_n * 64 + (lane >> 4) * 8 + (lane & 7);
    const int b_sel = (lane >> 3) & 1;
    uint32_t aoff[2][2], boff[2][4];
    #pragma unroll
    for (int ks = 0; ks < 2; ++ks) {
        #pragma unroll
        for (int mf = 0; mf < 2; ++mf)
            aoff[ks][mf] = sw64((uint32_t)((a_row + mf * 16) * 64 + (ks * 2 + a_sel) * 16));
        #pragma unroll
        for (int nfp = 0; nfp < 4; ++nfp)
            boff[ks][nfp] = sw64((uint32_t)((b_row + nfp * 16) * 64 + (ks * 2 + b_sel) * 16));
    }

    // ---- prologue: fill stages 0..2, decode stage 0 ----
    fill(0); cp_commit();
    fill(1); cp_commit();
    fill(2); cp_commit();
    asm volatile("cp.async.wait_group 2;" ::: "memory");
    decode(0);
    __syncthreads();

    // ---- mainloop: one __syncthreads per iteration ----
    for (int t = 0; t < NITER; ++t) {
        asm volatile("cp.async.wait_group 1;" ::: "memory");
        if (t + 1 < NITER) decode(t + 1);
        if (t + 3 < NITER) fill(t + 3);
        cp_commit();

        const uint32_t Xb = sb + OFF_X + (uint32_t)(t & 3) * 8192;
        const uint32_t Wb = sb + OFF_W + (uint32_t)(t & 1) * 8192;
        #pragma unroll
        for (int ks = 0; ks < 2; ++ks) {
            uint32_t a[2][4], b[4][4];
            ldsm4(a[0], Xb + aoff[ks][0]);
            ldsm4(a[1], Xb + aoff[ks][1]);
            #pragma unroll
            for (int nfp = 0; nfp < 4; ++nfp) ldsm4(b[nfp], Wb + boff[ks][nfp]);
            #pragma unroll
            for (int nfp = 0; nfp < 4; ++nfp) {
                mma_tf32(acc[0][nfp * 2],     a[0], &b[nfp][0]);
                mma_tf32(acc[1][nfp * 2],     a[1], &b[nfp][0]);
                mma_tf32(acc[0][nfp * 2 + 1], a[0], &b[nfp][2]);
                mma_tf32(acc[1][nfp * 2 + 1], a[1], &b[nfp][2]);
            }
        }
        __syncthreads();
    }

    // ---- epilogue: (acc + bias) * scale ----
    #pragma unroll
    for (int mf = 0; mf < 2; ++mf) {
        const int row = m0 + warp_m * 32 + mf * 16 + (lane >> 2);
        #pragma unroll
        for (int nf = 0; nf < 8; ++nf) {
            const int cl = warp_n * 64 + nf * 8 + (lane & 3) * 2;
            float2 v0, v1;
            v0.x = (acc[mf][nf][0] + bi_s[cl])     * sc_s[cl];
            v0.y = (acc[mf][nf][1] + bi_s[cl + 1]) * sc_s[cl + 1];
            v1.x = (acc[mf][nf][2] + bi_s[cl])     * sc_s[cl];
            v1.y = (acc[mf][nf][3] + bi_s[cl + 1]) * sc_s[cl + 1];
            *(float2*)(out + (size_t)row * OUT_ + n0 + cl)       = v0;
            *(float2*)(out + (size_t)(row + 8) * OUT_ + n0 + cl) = v1;
        }
    }
}

// ----------------------------------------------------------------------------
extern "C" void kernel_launch(void* const* d_in, const int* in_sizes, int n_in,
                              void* d_out, int out_size) {
    const float* x      = (const float*)d_in[0];
    const int*   stored = (const int*)d_in[1];
    const int*   sgn    = (const int*)d_in[2];
    const float* lmn    = (const float*)d_in[3];
    const float* lmx    = (const float*)d_in[4];
    const float* scale  = (const float*)d_in[5];
    const float* bias   = (const float*)d_in[6];
    float* out = (float*)d_out;

    cudaFuncSetAttribute(qins_gemm_kernel,
                         cudaFuncAttributeMaxDynamicSharedMemorySize, SMEM_TOTAL);

    xr_kernel<<<(B_ * IN_) / 256, 256>>>(x);
    qins_gemm_kernel<<<GRID, 256, SMEM_TOTAL>>>(stored, sgn, lmn, lmx, scale, bias, out);
}